// round 14
// baseline (speedup 1.0000x reference)
#include <cuda_runtime.h>
#include <cuda_fp16.h>
#include <cstdint>
#include <math.h>

#define Hh 128
#define Ww 128
#define Ho 126
#define Wo 126
#define HOWO (126*126)
#define NCH 36              // 9 taps * 4 chunks of 32 channels

// fp16 copy of the input image: [n][c][y][x], plane = 16384 halfs
__device__ __half g_img[8 * 128 * 128 * 128];

// B-fragment-ordered fp16 weights:
// [ch(36)][ncol(4)][ni(4)][lane(32)][4 u32] ; each u32 slot = {g0r0,g0r1,g1r0,g1r1}
__device__ __half g_wt[NCH * 4 * 4 * 32 * 8];

__device__ __forceinline__ uint32_t smem_u32(const void* p) {
    uint32_t a;
    asm("{ .reg .u64 t; cvta.to.shared.u64 t, %1; cvt.u32.u64 %0, t; }" : "=r"(a) : "l"(p));
    return a;
}

// ---------------------------------------------------------------------------
// Image prep: fp32 -> fp16, vectorized (float4 in, 8B out per thread)
// ---------------------------------------------------------------------------
__global__ void img_prep(const float* __restrict__ inp) {
    int i = blockIdx.x * blockDim.x + threadIdx.x;   // 4.19M threads
    float4 v = ((const float4*)inp)[i];
    __half2 a = __floats2half2_rn(v.x, v.y);
    __half2 b = __floats2half2_rn(v.z, v.w);
    ((__half2*)g_img)[2 * i]     = a;
    ((__half2*)g_img)[2 * i + 1] = b;
}

// ---------------------------------------------------------------------------
// Weight prep: w[o][c][kh][kw] -> fp16, direct B-fragment layout
// ---------------------------------------------------------------------------
__global__ void wt_prep(const float* __restrict__ w) {
    int id = blockIdx.x * blockDim.x + threadIdx.x;
    if (id >= 9 * 128 * 128) return;
    int o = id & 127, c = (id >> 7) & 127, tap = id >> 14;
    int ch = tap * 4 + (c >> 5);
    int k  = c & 31;
    int g  = k >> 4;
    int kk = k & 15;
    int r  = (kk >= 8) ? 1 : 0;
    int kk8 = kk & 7;
    int j = kk8 >> 1, half = kk8 & 1;
    int ncol = o >> 5;
    int oo = o & 31;
    int ni = oo >> 3, nn = oo & 7;
    int lane = nn * 4 + j;
    int u32idx = (((ch * 4 + ncol) * 4 + ni) * 32 + lane) * 4 + g * 2 + r;
    g_wt[u32idx * 2 + half] = __float2half_rn(w[(o * 128 + c) * 9 + tap]);
}

// ---------------------------------------------------------------------------
// Main kernel: CTA per (ho, n). D[pix 128, co 128] fp16 m16n8k16.
// 8 warps = 2 m-rows x 4 n-cols, warp tile M64 x N32. B direct from gmem.
// Gather reads fp16 image (half the L1 lines per corner load).
// ---------------------------------------------------------------------------
__global__ void __launch_bounds__(256, 2)
adc_mma(const float* __restrict__ rates,
        const float* __restrict__ bias, float* __restrict__ out)
{
    __shared__ uint32_t sampS[2][2][128][8];   // [buf][g][pix][8 u32]  16KB
    __shared__ float rbuf[128];

    const int t = threadIdx.x, lane = t & 31, wrp = t >> 5;
    const int ho = blockIdx.x, n = blockIdx.y;

    // rate map: bilinear upsample rates[32x32] -> (ho, pix)
    if (t < 128) {
        const float scale = (float)(32.0 / 126.0);
        float sy = fminf(fmaxf(((float)ho + 0.5f) * scale - 0.5f, 0.0f), 31.0f);
        float sx = fminf(fmaxf(((float)t  + 0.5f) * scale - 0.5f, 0.0f), 31.0f);
        float y0f = floorf(sy), x0f = floorf(sx);
        int y0 = (int)y0f, x0 = (int)x0f;
        int y1 = min(y0 + 1, 31), x1 = min(x0 + 1, 31);
        float wy = sy - y0f, wx = sx - x0f;
        rbuf[t] = rates[y0 * 32 + x0] * (1.f - wy) * (1.f - wx)
                + rates[y0 * 32 + x1] * (1.f - wy) * wx
                + rates[y1 * 32 + x0] * wy * (1.f - wx)
                + rates[y1 * 32 + x1] * wy * wx;
    }
    __syncthreads();

    const int pix = t & 127, kg = t >> 7;
    const float rate = rbuf[pix];
    const float fvalid = (pix < Wo) ? 1.0f : 0.0f;

    // bilinear coeffs for current tap (register resident, fixed pix per thread)
    float cw0, cw1, cw2, cw3;
    int o0, o1, o2, o3;
    auto calc = [&](int tap) {
        int kh = tap / 3, kw = tap - kh * 3;
        float fy = (float)ho  + (float)kh * rate;
        float fx = (float)pix + (float)kw * rate;
        float y0f = floorf(fy), x0f = floorf(fx);
        float wy = fy - y0f, wx = fx - x0f;
        int y0 = (int)y0f, x0 = (int)x0f;
        int y1 = y0 + 1,  x1 = x0 + 1;
        float my0 = (y0 >= 0 && y0 < Hh) ? 1.f : 0.f;
        float my1 = (y1 >= 0 && y1 < Hh) ? 1.f : 0.f;
        float mx0 = (x0 >= 0 && x0 < Ww) ? 1.f : 0.f;
        float mx1 = (x1 >= 0 && x1 < Ww) ? 1.f : 0.f;
        cw0 = (1.f - wy) * (1.f - wx) * my0 * mx0 * fvalid;
        cw1 = (1.f - wy) * wx         * my0 * mx1 * fvalid;
        cw2 = wy * (1.f - wx)         * my1 * mx0 * fvalid;
        cw3 = wy * wx                 * my1 * mx1 * fvalid;
        int y0c = min(max(y0, 0), Hh - 1), y1c = min(max(y1, 0), Hh - 1);
        int x0c = min(max(x0, 0), Ww - 1), x1c = min(max(x1, 0), Ww - 1);
        o0 = y0c * Ww + x0c; o1 = y0c * Ww + x1c;
        o2 = y1c * Ww + x0c; o3 = y1c * Ww + x1c;
    };

    uint32_t ug[2][4];      // gathered fp16x2 slots, per g group
    auto gather = [&](int ch) {
        const int cb = n * 128 + (ch & 3) * 32;
        #pragma unroll
        for (int g = 0; g < 2; g++) {
            const __half* pg = g_img + ((size_t)(cb + g * 16) << 14);
            #pragma unroll
            for (int s = 0; s < 4; s++) {
                int S  = 4 * kg + s;
                int kA = (S & 1) ? (S + 7) : S;
                const __half* p = pg + ((size_t)kA << 14);
                float e = cw0 * __half2float(__ldg(p + o0))
                        + cw1 * __half2float(__ldg(p + o1))
                        + cw2 * __half2float(__ldg(p + o2))
                        + cw3 * __half2float(__ldg(p + o3));
                const __half* q = p + 16384;
                float od = cw0 * __half2float(__ldg(q + o0))
                         + cw1 * __half2float(__ldg(q + o1))
                         + cw2 * __half2float(__ldg(q + o2))
                         + cw3 * __half2float(__ldg(q + o3));
                asm("cvt.rn.f16x2.f32 %0, %1, %2;" : "=r"(ug[g][s]) : "f"(od), "f"(e));
            }
        }
    };

    calc(0);
    gather(0);

    // warp tile: M64 x N32 ; warps = 2 m-rows x 4 n-cols
    const int m0   = (wrp & 1) * 64;
    const int ncol = wrp >> 1;
    const int n0   = ncol * 32;

    // accumulators init = bias
    float acc[4][4][4];
    #pragma unroll
    for (int ni = 0; ni < 4; ni++) {
        int cb = n0 + ni * 8 + (lane & 3) * 2;
        float b0 = __ldg(bias + cb), b1 = __ldg(bias + cb + 1);
        #pragma unroll
        for (int mi = 0; mi < 4; mi++) {
            acc[mi][ni][0] = b0; acc[mi][ni][1] = b1;
            acc[mi][ni][2] = b0; acc[mi][ni][3] = b1;
        }
    }

    const uint32_t sa = smem_u32(sampS);
    const uint32_t xorv = (pix & 4) << 2;    // 16B-half XOR swizzle
    // B fragment gmem base for this warp (per-lane)
    const uint4* gb = (const uint4*)g_wt + (size_t)ncol * 128 + lane;

    for (int ch = 0; ch < NCH; ch++) {
        const int st = ch & 1;
        const uint32_t sbase = sa + st * 8192;

        // ---- STS gathered fp16 samples (from prev gather) ----
        #pragma unroll
        for (int g = 0; g < 2; g++) {
            uint32_t a1 = sbase + (uint32_t)(g * 128 + pix) * 32
                        + ((uint32_t)(kg * 16) ^ xorv);
            asm volatile("st.shared.v4.b32 [%0], {%1,%2,%3,%4};"
                         :: "r"(a1), "r"(ug[g][0]), "r"(ug[g][1]),
                            "r"(ug[g][2]), "r"(ug[g][3]));
        }
        __syncthreads();   // publishes buf[st]; guards buf[st^1] overwrite next iter

        // ---- B fragments: direct LDG.128 from fragment-ordered gmem ----
        uint4 br[4];
        {
            const uint4* gp = gb + (size_t)ch * 512;
            #pragma unroll
            for (int nl = 0; nl < 4; nl++)
                br[nl] = __ldg(gp + nl * 32);
        }

        // ---- issue next gather (LDGs overlap MMA across warps) ----
        if (ch < NCH - 1) {
            int c1 = ch + 1;
            if ((c1 & 3) == 0) calc(c1 >> 2);
            gather(c1);
        }

        // ---- MMA: 2 k16-groups x (4 m16 x 4 n8) ----
        #pragma unroll
        for (int g = 0; g < 2; g++) {
            const uint32_t ab = sbase + (uint32_t)g * 4096;
            const uint32_t k8off = (lane & 3) * 8;
            uint32_t A[4][4];
            #pragma unroll
            for (int mi = 0; mi < 4; mi++) {
                int r0 = m0 + mi * 16 + (lane >> 2);
                int r1 = r0 + 8;
                uint32_t ad0 = ab + (uint32_t)r0 * 32 + (k8off ^ ((r0 & 4) << 2));
                uint32_t ad1 = ab + (uint32_t)r1 * 32 + (k8off ^ ((r1 & 4) << 2));
                asm volatile("ld.shared.v2.b32 {%0,%1}, [%2];"
                             : "=r"(A[mi][0]), "=r"(A[mi][2]) : "r"(ad0));
                asm volatile("ld.shared.v2.b32 {%0,%1}, [%2];"
                             : "=r"(A[mi][1]), "=r"(A[mi][3]) : "r"(ad1));
            }
            #pragma unroll
            for (int ni = 0; ni < 4; ni++) {
                uint32_t B0 = (g == 0) ? br[ni].x : br[ni].z;
                uint32_t B1 = (g == 0) ? br[ni].y : br[ni].w;
                #pragma unroll
                for (int mi = 0; mi < 4; mi++) {
                    asm volatile(
                        "mma.sync.aligned.m16n8k16.row.col.f32.f16.f16.f32 "
                        "{%0,%1,%2,%3}, {%4,%5,%6,%7}, {%8,%9}, {%0,%1,%2,%3};"
                        : "+f"(acc[mi][ni][0]), "+f"(acc[mi][ni][1]),
                          "+f"(acc[mi][ni][2]), "+f"(acc[mi][ni][3])
                        : "r"(A[mi][0]), "r"(A[mi][1]), "r"(A[mi][2]), "r"(A[mi][3]),
                          "r"(B0), "r"(B1));
                }
            }
        }
    }

    // ---- epilogue: scatter C frags to out[n][co][ho][wo] ----
    #pragma unroll
    for (int mi = 0; mi < 4; mi++) {
        int r0 = m0 + mi * 16 + (lane >> 2);
        int r1 = r0 + 8;
        #pragma unroll
        for (int ni = 0; ni < 4; ni++) {
            int co = n0 + ni * 8 + (lane & 3) * 2;
            float* p0 = out + (size_t)(n * 128 + co) * HOWO + ho * Wo;
            float* p1 = p0 + HOWO;
            if (r0 < Wo) { p0[r0] = acc[mi][ni][0]; p1[r0] = acc[mi][ni][1]; }
            if (r1 < Wo) { p0[r1] = acc[mi][ni][2]; p1[r1] = acc[mi][ni][3]; }
        }
    }
}

// ---------------------------------------------------------------------------
extern "C" void kernel_launch(void* const* d_in, const int* in_sizes, int n_in,
                              void* d_out, int out_size) {
    const float* inp   = (const float*)d_in[0];  // [8,128,128,128]
    const float* wgt   = (const float*)d_in[1];  // [128,128,3,3]
    const float* rates = (const float*)d_in[2];  // [1,1,32,32]
    const float* bias  = (const float*)d_in[3];  // [128]
    float* out = (float*)d_out;

    img_prep<<<(8 * 128 * 128 * 128 / 4) / 256, 256>>>(inp);
    wt_prep<<<(9 * 128 * 128 + 255) / 256, 256>>>(wgt);

    dim3 grid(Ho, 8);   // (126, 8) = 1008 CTAs
    adc_mma<<<grid, 256>>>(rates, bias, out);
}

// round 16
// speedup vs baseline: 1.0648x; 1.0648x over previous
#include <cuda_runtime.h>
#include <cuda_fp16.h>
#include <cstdint>
#include <math.h>

#define Hh 128
#define Ww 128
#define Ho 126
#define Wo 126
#define HOWO (126*126)
#define NCH 36              // 9 taps * 4 chunks of 32 channels

// Corner-quad fp16 image: [plane(1024)][y][x] -> {v(y,x),v(y,x+1),v(y+1,x),v(y+1,x+1)}
// 8 bytes per position; 134 MB static.
__device__ uint2 g_quad[8 * 128 * 128 * 128];

// B-fragment-ordered fp16 weights:
// [ch(36)][ncol(4)][ni(4)][lane(32)][4 u32] ; each u32 slot = {g0r0,g0r1,g1r0,g1r1}
__device__ __half g_wt[NCH * 4 * 4 * 32 * 8];

__device__ __forceinline__ uint32_t smem_u32(const void* p) {
    uint32_t a;
    asm("{ .reg .u64 t; cvta.to.shared.u64 t, %1; cvt.u32.u64 %0, t; }" : "=r"(a) : "l"(p));
    return a;
}

// ---------------------------------------------------------------------------
// Quad prep: fp32 image -> fp16 corner quads (one 8B quad per (plane,y,x))
// ---------------------------------------------------------------------------
__global__ void quad_prep(const float* __restrict__ inp) {
    int i = blockIdx.x * blockDim.x + threadIdx.x;   // 16.78M
    int xy = i & 16383, x = xy & 127, y = xy >> 7;
    const float* p = inp + ((size_t)(i >> 14) << 14);
    int x1 = min(x + 1, 127), y1 = min(y + 1, 127);
    __half2 lo = __floats2half2_rn(p[y * 128 + x],  p[y * 128 + x1]);
    __half2 hi = __floats2half2_rn(p[y1 * 128 + x], p[y1 * 128 + x1]);
    uint2 q;
    q.x = *(const uint32_t*)&lo;
    q.y = *(const uint32_t*)&hi;
    g_quad[i] = q;
}

// ---------------------------------------------------------------------------
// Weight prep: w[o][c][kh][kw] -> fp16, direct B-fragment layout
// ---------------------------------------------------------------------------
__global__ void wt_prep(const float* __restrict__ w) {
    int id = blockIdx.x * blockDim.x + threadIdx.x;
    if (id >= 9 * 128 * 128) return;
    int o = id & 127, c = (id >> 7) & 127, tap = id >> 14;
    int ch = tap * 4 + (c >> 5);
    int k  = c & 31;
    int g  = k >> 4;
    int kk = k & 15;
    int r  = (kk >= 8) ? 1 : 0;
    int kk8 = kk & 7;
    int j = kk8 >> 1, half = kk8 & 1;
    int ncol = o >> 5;
    int oo = o & 31;
    int ni = oo >> 3, nn = oo & 7;
    int lane = nn * 4 + j;
    int u32idx = (((ch * 4 + ncol) * 4 + ni) * 32 + lane) * 4 + g * 2 + r;
    g_wt[u32idx * 2 + half] = __float2half_rn(w[(o * 128 + c) * 9 + tap]);
}

// ---------------------------------------------------------------------------
// Main kernel: CTA per (ho, n). D[pix 128, co 128] fp16 m16n8k16.
// 8 warps = 2 m-rows x 4 n-cols, warp tile M64 x N32. B direct from gmem.
// Bilinear gather: one LDG.64 corner-quad + 4-term dot per sample.
// ---------------------------------------------------------------------------
__global__ void __launch_bounds__(256, 2)
adc_mma(const float* __restrict__ rates,
        const float* __restrict__ bias, float* __restrict__ out)
{
    __shared__ uint32_t sampS[2][2][128][8];   // [buf][g][pix][8 u32]  16KB
    __shared__ float rbuf[128];

    const int t = threadIdx.x, lane = t & 31, wrp = t >> 5;
    const int ho = blockIdx.x, n = blockIdx.y;

    // rate map: bilinear upsample rates[32x32] -> (ho, pix)
    if (t < 128) {
        const float scale = (float)(32.0 / 126.0);
        float sy = fminf(fmaxf(((float)ho + 0.5f) * scale - 0.5f, 0.0f), 31.0f);
        float sx = fminf(fmaxf(((float)t  + 0.5f) * scale - 0.5f, 0.0f), 31.0f);
        float y0f = floorf(sy), x0f = floorf(sx);
        int y0 = (int)y0f, x0 = (int)x0f;
        int y1 = min(y0 + 1, 31), x1 = min(x0 + 1, 31);
        float wy = sy - y0f, wx = sx - x0f;
        rbuf[t] = rates[y0 * 32 + x0] * (1.f - wy) * (1.f - wx)
                + rates[y0 * 32 + x1] * (1.f - wy) * wx
                + rates[y1 * 32 + x0] * wy * (1.f - wx)
                + rates[y1 * 32 + x1] * wy * wx;
    }
    __syncthreads();

    const int pix = t & 127, kg = t >> 7;
    const float rate = rbuf[pix];
    const float fvalid = (pix < Wo) ? 1.0f : 0.0f;

    // per-tap quad coefficients + base offset (register resident)
    float cq0, cq1, cq2, cq3;
    int obase;
    auto calc = [&](int tap) {
        int kh = tap / 3, kw = tap - kh * 3;
        float fy = (float)ho  + (float)kh * rate;
        float fx = (float)pix + (float)kw * rate;
        float y0f = floorf(fy), x0f = floorf(fx);
        float wy = fy - y0f, wx = fx - x0f;
        int y0 = (int)y0f, x0 = (int)x0f;        // always >= 0 here
        int y1 = y0 + 1,  x1 = x0 + 1;
        float my0 = (y0 < Hh) ? 1.f : 0.f;
        float my1 = (y1 < Hh) ? 1.f : 0.f;
        float mx0 = (x0 < Ww) ? 1.f : 0.f;
        float mx1 = (x1 < Ww) ? 1.f : 0.f;
        float cw0 = (1.f - wy) * (1.f - wx) * my0 * mx0 * fvalid;
        float cw1 = (1.f - wy) * wx         * my0 * mx1 * fvalid;
        float cw2 = wy * (1.f - wx)         * my1 * mx0 * fvalid;
        float cw3 = wy * wx                 * my1 * mx1 * fvalid;
        int yb = min(y0, 126), xb = min(x0, 126);
        // slot index: row (y==yb ? 0 : 1), col (x==xb ? 0 : 1); masked taps may
        // collide into occupied slots but carry zero coefficient.
        int r0 = (y0 == yb) ? 0 : 1, r1 = (y1 == yb + 1) ? 1 : ((y1 == yb) ? 0 : 1);
        int c0 = (x0 == xb) ? 0 : 1, c1 = (x1 == xb + 1) ? 1 : ((x1 == xb) ? 0 : 1);
        float q[4] = {0.f, 0.f, 0.f, 0.f};
        q[r0 * 2 + c0] += cw0;
        q[r0 * 2 + c1] += cw1;
        q[r1 * 2 + c0] += cw2;
        q[r1 * 2 + c1] += cw3;
        cq0 = q[0]; cq1 = q[1]; cq2 = q[2]; cq3 = q[3];
        obase = yb * 128 + xb;
    };

    uint32_t ug[2][4];      // gathered fp16x2 slots, per g group
    auto gather = [&](int ch) {
        const int cb = n * 128 + (ch & 3) * 32;
        #pragma unroll
        for (int g = 0; g < 2; g++) {
            const uint2* pg = g_quad + (((size_t)(cb + g * 16)) << 14) + obase;
            #pragma unroll
            for (int s = 0; s < 4; s++) {
                int S  = 4 * kg + s;
                int kA = (S & 1) ? (S + 7) : S;
                const uint2* p = pg + ((size_t)kA << 14);
                uint2 q0 = __ldg(p);
                uint2 q1 = __ldg(p + 16384);
                float2 a0 = __half22float2(*(const __half2*)&q0.x);
                float2 a1 = __half22float2(*(const __half2*)&q0.y);
                float2 b0 = __half22float2(*(const __half2*)&q1.x);
                float2 b1 = __half22float2(*(const __half2*)&q1.y);
                float e  = cq0 * a0.x + cq1 * a0.y + cq2 * a1.x + cq3 * a1.y;
                float od = cq0 * b0.x + cq1 * b0.y + cq2 * b1.x + cq3 * b1.y;
                asm("cvt.rn.f16x2.f32 %0, %1, %2;" : "=r"(ug[g][s]) : "f"(od), "f"(e));
            }
        }
    };

    calc(0);
    gather(0);

    // warp tile: M64 x N32 ; warps = 2 m-rows x 4 n-cols
    const int m0   = (wrp & 1) * 64;
    const int ncol = wrp >> 1;
    const int n0   = ncol * 32;

    // accumulators init = bias
    float acc[4][4][4];
    #pragma unroll
    for (int ni = 0; ni < 4; ni++) {
        int cb = n0 + ni * 8 + (lane & 3) * 2;
        float b0 = __ldg(bias + cb), b1 = __ldg(bias + cb + 1);
        #pragma unroll
        for (int mi = 0; mi < 4; mi++) {
            acc[mi][ni][0] = b0; acc[mi][ni][1] = b1;
            acc[mi][ni][2] = b0; acc[mi][ni][3] = b1;
        }
    }

    const uint32_t sa = smem_u32(sampS);
    const uint32_t xorv = (pix & 4) << 2;    // 16B-half XOR swizzle
    const uint4* gb = (const uint4*)g_wt + (size_t)ncol * 128 + lane;

    for (int ch = 0; ch < NCH; ch++) {
        const int st = ch & 1;
        const uint32_t sbase = sa + st * 8192;

        // ---- STS gathered fp16 samples (from prev gather) ----
        #pragma unroll
        for (int g = 0; g < 2; g++) {
            uint32_t a1 = sbase + (uint32_t)(g * 128 + pix) * 32
                        + ((uint32_t)(kg * 16) ^ xorv);
            asm volatile("st.shared.v4.b32 [%0], {%1,%2,%3,%4};"
                         :: "r"(a1), "r"(ug[g][0]), "r"(ug[g][1]),
                            "r"(ug[g][2]), "r"(ug[g][3]));
        }
        __syncthreads();   // publishes buf[st]; guards buf[st^1] overwrite next iter

        // ---- B fragments: direct LDG.128 from fragment-ordered gmem ----
        uint4 br[4];
        {
            const uint4* gp = gb + (size_t)ch * 512;
            #pragma unroll
            for (int nl = 0; nl < 4; nl++)
                br[nl] = __ldg(gp + nl * 32);
        }

        // ---- issue next gather (LDGs overlap MMA across warps) ----
        if (ch < NCH - 1) {
            int c1 = ch + 1;
            if ((c1 & 3) == 0) calc(c1 >> 2);
            gather(c1);
        }

        // ---- MMA: 2 k16-groups x (4 m16 x 4 n8) ----
        #pragma unroll
        for (int g = 0; g < 2; g++) {
            const uint32_t ab = sbase + (uint32_t)g * 4096;
            const uint32_t k8off = (lane & 3) * 8;
            uint32_t A[4][4];
            #pragma unroll
            for (int mi = 0; mi < 4; mi++) {
                int r0 = m0 + mi * 16 + (lane >> 2);
                int r1 = r0 + 8;
                uint32_t ad0 = ab + (uint32_t)r0 * 32 + (k8off ^ ((r0 & 4) << 2));
                uint32_t ad1 = ab + (uint32_t)r1 * 32 + (k8off ^ ((r1 & 4) << 2));
                asm volatile("ld.shared.v2.b32 {%0,%1}, [%2];"
                             : "=r"(A[mi][0]), "=r"(A[mi][2]) : "r"(ad0));
                asm volatile("ld.shared.v2.b32 {%0,%1}, [%2];"
                             : "=r"(A[mi][1]), "=r"(A[mi][3]) : "r"(ad1));
            }
            #pragma unroll
            for (int ni = 0; ni < 4; ni++) {
                uint32_t B0 = (g == 0) ? br[ni].x : br[ni].z;
                uint32_t B1 = (g == 0) ? br[ni].y : br[ni].w;
                #pragma unroll
                for (int mi = 0; mi < 4; mi++) {
                    asm volatile(
                        "mma.sync.aligned.m16n8k16.row.col.f32.f16.f16.f32 "
                        "{%0,%1,%2,%3}, {%4,%5,%6,%7}, {%8,%9}, {%0,%1,%2,%3};"
                        : "+f"(acc[mi][ni][0]), "+f"(acc[mi][ni][1]),
                          "+f"(acc[mi][ni][2]), "+f"(acc[mi][ni][3])
                        : "r"(A[mi][0]), "r"(A[mi][1]), "r"(A[mi][2]), "r"(A[mi][3]),
                          "r"(B0), "r"(B1));
                }
            }
        }
    }

    // ---- epilogue: scatter C frags to out[n][co][ho][wo] ----
    #pragma unroll
    for (int mi = 0; mi < 4; mi++) {
        int r0 = m0 + mi * 16 + (lane >> 2);
        int r1 = r0 + 8;
        #pragma unroll
        for (int ni = 0; ni < 4; ni++) {
            int co = n0 + ni * 8 + (lane & 3) * 2;
            float* p0 = out + (size_t)(n * 128 + co) * HOWO + ho * Wo;
            float* p1 = p0 + HOWO;
            if (r0 < Wo) { p0[r0] = acc[mi][ni][0]; p1[r0] = acc[mi][ni][1]; }
            if (r1 < Wo) { p0[r1] = acc[mi][ni][2]; p1[r1] = acc[mi][ni][3]; }
        }
    }
}

// ---------------------------------------------------------------------------
extern "C" void kernel_launch(void* const* d_in, const int* in_sizes, int n_in,
                              void* d_out, int out_size) {
    const float* inp   = (const float*)d_in[0];  // [8,128,128,128]
    const float* wgt   = (const float*)d_in[1];  // [128,128,3,3]
    const float* rates = (const float*)d_in[2];  // [1,1,32,32]
    const float* bias  = (const float*)d_in[3];  // [128]
    float* out = (float*)d_out;

    quad_prep<<<(8 * 128 * 128 * 128) / 256, 256>>>(inp);
    wt_prep<<<(9 * 128 * 128 + 255) / 256, 256>>>(wgt);

    dim3 grid(Ho, 8);   // (126, 8) = 1008 CTAs
    adc_mma<<<grid, 256>>>(rates, bias, out);
}

// round 17
// speedup vs baseline: 1.1204x; 1.0522x over previous
#include <cuda_runtime.h>
#include <cuda_fp16.h>
#include <cstdint>
#include <math.h>

#define Hh 128
#define Ww 128
#define Ho 126
#define Wo 126
#define HOWO (126*126)
#define NCH 36              // 9 taps * 4 chunks of 32 channels

// Corner-quad fp16 image: [plane(1024)][y][x] -> {v(y,x),v(y,x+1),v(y+1,x),v(y+1,x+1)}
__device__ uint2 g_quad[8 * 128 * 128 * 128];

// B-fragment-ordered fp16 weights:
// [ch(36)][ncol(4)][ni(4)][lane(32)][4 u32] ; u32 slot = {g0b0,g0b1,g1b0,g1b1}
__device__ __half g_wt[NCH * 4 * 4 * 32 * 8];

__device__ __forceinline__ uint32_t smem_u32(const void* p) {
    uint32_t a;
    asm("{ .reg .u64 t; cvta.to.shared.u64 t, %1; cvt.u32.u64 %0, t; }" : "=r"(a) : "l"(p));
    return a;
}

// ---------------------------------------------------------------------------
// Quad prep v2: 4 quads per thread via vectorized row loads
// ---------------------------------------------------------------------------
__global__ void quad_prep(const float* __restrict__ inp) {
    int i = blockIdx.x * blockDim.x + threadIdx.x;     // 4.19M threads
    int xb = (i & 31) << 2;                            // 0,4,...,124
    int yp = i >> 5;                                   // plane*128 + y
    int y  = yp & 127;
    const float* pb = inp + ((size_t)(yp >> 7) << 14);
    const float* r0 = pb + y * 128;
    const float* r1 = pb + min(y + 1, 127) * 128;
    float4 a = *(const float4*)(r0 + xb);
    float4 b = *(const float4*)(r1 + xb);
    int nx = min(xb + 4, 127);
    float a4 = __ldg(r0 + nx), b4 = __ldg(r1 + nx);
    uint2 q[4];
    {
        __half2 t0, t1;
        t0 = __floats2half2_rn(a.x, a.y); t1 = __floats2half2_rn(b.x, b.y);
        q[0].x = *(uint32_t*)&t0; q[0].y = *(uint32_t*)&t1;
        t0 = __floats2half2_rn(a.y, a.z); t1 = __floats2half2_rn(b.y, b.z);
        q[1].x = *(uint32_t*)&t0; q[1].y = *(uint32_t*)&t1;
        t0 = __floats2half2_rn(a.z, a.w); t1 = __floats2half2_rn(b.z, b.w);
        q[2].x = *(uint32_t*)&t0; q[2].y = *(uint32_t*)&t1;
        t0 = __floats2half2_rn(a.w, a4);  t1 = __floats2half2_rn(b.w, b4);
        q[3].x = *(uint32_t*)&t0; q[3].y = *(uint32_t*)&t1;
    }
    uint4* dst = (uint4*)(g_quad + ((size_t)yp << 7) + xb);
    dst[0] = make_uint4(q[0].x, q[0].y, q[1].x, q[1].y);
    dst[1] = make_uint4(q[2].x, q[2].y, q[3].x, q[3].y);
}

// ---------------------------------------------------------------------------
// Weight prep: w[o][c][kh][kw] -> fp16, direct B-fragment layout (unchanged)
// ---------------------------------------------------------------------------
__global__ void wt_prep(const float* __restrict__ w) {
    int id = blockIdx.x * blockDim.x + threadIdx.x;
    if (id >= 9 * 128 * 128) return;
    int o = id & 127, c = (id >> 7) & 127, tap = id >> 14;
    int ch = tap * 4 + (c >> 5);
    int k  = c & 31;
    int g  = k >> 4;
    int kk = k & 15;
    int r  = (kk >= 8) ? 1 : 0;
    int kk8 = kk & 7;
    int j = kk8 >> 1, half = kk8 & 1;
    int ncol = o >> 5;
    int oo = o & 31;
    int ni = oo >> 3, nn = oo & 7;
    int lane = nn * 4 + j;
    int u32idx = (((ch * 4 + ncol) * 4 + ni) * 32 + lane) * 4 + g * 2 + r;
    g_wt[u32idx * 2 + half] = __float2half_rn(w[(o * 128 + c) * 9 + tap]);
}

// ---------------------------------------------------------------------------
// Main kernel: CTA per (ho, n). D[pix 128, co 128] fp16 m16n8k16.
// A tile in smem PLAIN k-order, loaded via ldmatrix.x4. B direct from gmem.
// ---------------------------------------------------------------------------
__global__ void __launch_bounds__(256, 2)
adc_mma(const float* __restrict__ rates,
        const float* __restrict__ bias, float* __restrict__ out)
{
    __shared__ uint32_t sampS[2][2][128][8];   // [buf][g][pix][8 u32] plain k-order
    __shared__ float rbuf[128];

    const int t = threadIdx.x, lane = t & 31, wrp = t >> 5;
    const int ho = blockIdx.x, n = blockIdx.y;

    // rate map: bilinear upsample rates[32x32] -> (ho, pix)
    if (t < 128) {
        const float scale = (float)(32.0 / 126.0);
        float sy = fminf(fmaxf(((float)ho + 0.5f) * scale - 0.5f, 0.0f), 31.0f);
        float sx = fminf(fmaxf(((float)t  + 0.5f) * scale - 0.5f, 0.0f), 31.0f);
        float y0f = floorf(sy), x0f = floorf(sx);
        int y0 = (int)y0f, x0 = (int)x0f;
        int y1 = min(y0 + 1, 31), x1 = min(x0 + 1, 31);
        float wy = sy - y0f, wx = sx - x0f;
        rbuf[t] = rates[y0 * 32 + x0] * (1.f - wy) * (1.f - wx)
                + rates[y0 * 32 + x1] * (1.f - wy) * wx
                + rates[y1 * 32 + x0] * wy * (1.f - wx)
                + rates[y1 * 32 + x1] * wy * wx;
    }
    __syncthreads();

    const int pix = t & 127, kg = t >> 7;
    const float rate = rbuf[pix];
    const float fvalid = (pix < Wo) ? 1.0f : 0.0f;

    // per-tap quad coefficients + base offset (register resident)
    float cq0, cq1, cq2, cq3;
    int obase;
    auto calc = [&](int tap) {
        int kh = tap / 3, kw = tap - kh * 3;
        float fy = (float)ho  + (float)kh * rate;
        float fx = (float)pix + (float)kw * rate;
        float y0f = floorf(fy), x0f = floorf(fx);
        float wy = fy - y0f, wx = fx - x0f;
        int y0 = (int)y0f, x0 = (int)x0f;        // >= 0 always
        int y1 = y0 + 1,  x1 = x0 + 1;
        float my0 = (y0 < Hh) ? 1.f : 0.f;
        float my1 = (y1 < Hh) ? 1.f : 0.f;
        float mx0 = (x0 < Ww) ? 1.f : 0.f;
        float mx1 = (x1 < Ww) ? 1.f : 0.f;
        float cw0 = (1.f - wy) * (1.f - wx) * my0 * mx0 * fvalid;
        float cw1 = (1.f - wy) * wx         * my0 * mx1 * fvalid;
        float cw2 = wy * (1.f - wx)         * my1 * mx0 * fvalid;
        float cw3 = wy * wx                 * my1 * mx1 * fvalid;
        int yb = min(y0, 126), xb = min(x0, 126);
        int r0 = (y0 == yb) ? 0 : 1, r1 = (y1 == yb + 1) ? 1 : ((y1 == yb) ? 0 : 1);
        int c0 = (x0 == xb) ? 0 : 1, c1 = (x1 == xb + 1) ? 1 : ((x1 == xb) ? 0 : 1);
        float q[4] = {0.f, 0.f, 0.f, 0.f};
        q[r0 * 2 + c0] += cw0;
        q[r0 * 2 + c1] += cw1;
        q[r1 * 2 + c0] += cw2;
        q[r1 * 2 + c1] += cw3;
        cq0 = q[0]; cq1 = q[1]; cq2 = q[2]; cq3 = q[3];
        obase = yb * 128 + xb;
    };

    uint32_t ug[2][4];      // gathered fp16x2, plain order: slot s = k{8kg+2s, +1}
    auto gather = [&](int ch) {
        const int cb = n * 128 + (ch & 3) * 32;
        #pragma unroll
        for (int g = 0; g < 2; g++) {
            const uint2* pg = g_quad + (((size_t)(cb + g * 16)) << 14) + obase;
            #pragma unroll
            for (int s = 0; s < 4; s++) {
                int kA = 8 * kg + 2 * s;            // plain k-order
                const uint2* p = pg + ((size_t)kA << 14);
                uint2 q0 = __ldg(p);
                uint2 q1 = __ldg(p + 16384);
                float2 a0 = __half22float2(*(const __half2*)&q0.x);
                float2 a1 = __half22float2(*(const __half2*)&q0.y);
                float2 b0 = __half22float2(*(const __half2*)&q1.x);
                float2 b1 = __half22float2(*(const __half2*)&q1.y);
                float e  = cq0 * a0.x + cq1 * a0.y + cq2 * a1.x + cq3 * a1.y;
                float od = cq0 * b0.x + cq1 * b0.y + cq2 * b1.x + cq3 * b1.y;
                asm("cvt.rn.f16x2.f32 %0, %1, %2;" : "=r"(ug[g][s]) : "f"(od), "f"(e));
            }
        }
    };

    calc(0);
    gather(0);

    // warp tile: M64 x N32 ; warps = 2 m-rows x 4 n-cols
    const int m0   = (wrp & 1) * 64;
    const int ncol = wrp >> 1;
    const int n0   = ncol * 32;

    // accumulators init = bias
    float acc[4][4][4];
    #pragma unroll
    for (int ni = 0; ni < 4; ni++) {
        int cb = n0 + ni * 8 + (lane & 3) * 2;
        float b0 = __ldg(bias + cb), b1 = __ldg(bias + cb + 1);
        #pragma unroll
        for (int mi = 0; mi < 4; mi++) {
            acc[mi][ni][0] = b0; acc[mi][ni][1] = b1;
            acc[mi][ni][2] = b0; acc[mi][ni][3] = b1;
        }
    }

    const uint32_t sa = smem_u32(sampS);
    const uint32_t xorv = (pix & 4) << 2;    // store-side 16B-half XOR swizzle
    // ldmatrix per-lane base: row = m0 + ((lane>>3)&1)*8 + (lane&7), khalf = lane>>4
    const uint32_t lmbase = sa
        + (uint32_t)(m0 + ((lane >> 3) & 1) * 8 + (lane & 7)) * 32
        + (((uint32_t)(lane >> 4) * 16) ^ ((uint32_t)(lane & 4) << 2));
    const uint4* gb = (const uint4*)g_wt + (size_t)ncol * 128 + lane;

    for (int ch = 0; ch < NCH; ch++) {
        const int st = ch & 1;
        const uint32_t sbase = sa + st * 8192;

        // ---- STS gathered fp16 samples (plain k-order) ----
        #pragma unroll
        for (int g = 0; g < 2; g++) {
            uint32_t a1 = sbase + (uint32_t)(g * 128 + pix) * 32
                        + ((uint32_t)(kg * 16) ^ xorv);
            asm volatile("st.shared.v4.b32 [%0], {%1,%2,%3,%4};"
                         :: "r"(a1), "r"(ug[g][0]), "r"(ug[g][1]),
                            "r"(ug[g][2]), "r"(ug[g][3]));
        }
        __syncthreads();   // publishes buf[st]; guards buf[st^1] overwrite next iter

        // ---- B fragments: direct LDG.128 from fragment-ordered gmem ----
        uint4 br[4];
        {
            const uint4* gp = gb + (size_t)ch * 512;
            #pragma unroll
            for (int nl = 0; nl < 4; nl++)
                br[nl] = __ldg(gp + nl * 32);
        }

        // ---- issue next gather (LDGs overlap MMA across warps) ----
        if (ch < NCH - 1) {
            int c1 = ch + 1;
            if ((c1 & 3) == 0) calc(c1 >> 2);
            gather(c1);
        }

        // ---- MMA: 2 k16-groups x (4 m16 x 4 n8), A via ldmatrix.x4 ----
        #pragma unroll
        for (int g = 0; g < 2; g++) {
            const uint32_t lb = lmbase + st * 8192 + (uint32_t)g * 4096;
            uint32_t A[4][4];
            #pragma unroll
            for (int mi = 0; mi < 4; mi++) {
                asm volatile("ldmatrix.sync.aligned.m8n8.x4.shared.b16 "
                             "{%0,%1,%2,%3}, [%4];"
                             : "=r"(A[mi][0]), "=r"(A[mi][1]),
                               "=r"(A[mi][2]), "=r"(A[mi][3])
                             : "r"(lb + (uint32_t)mi * 512));
            }
            #pragma unroll
            for (int ni = 0; ni < 4; ni++) {
                uint32_t B0 = (g == 0) ? br[ni].x : br[ni].z;
                uint32_t B1 = (g == 0) ? br[ni].y : br[ni].w;
                #pragma unroll
                for (int mi = 0; mi < 4; mi++) {
                    asm volatile(
                        "mma.sync.aligned.m16n8k16.row.col.f32.f16.f16.f32 "
                        "{%0,%1,%2,%3}, {%4,%5,%6,%7}, {%8,%9}, {%0,%1,%2,%3};"
                        : "+f"(acc[mi][ni][0]), "+f"(acc[mi][ni][1]),
                          "+f"(acc[mi][ni][2]), "+f"(acc[mi][ni][3])
                        : "r"(A[mi][0]), "r"(A[mi][1]), "r"(A[mi][2]), "r"(A[mi][3]),
                          "r"(B0), "r"(B1));
                }
            }
        }
    }

    // ---- epilogue: scatter C frags to out[n][co][ho][wo] ----
    #pragma unroll
    for (int mi = 0; mi < 4; mi++) {
        int r0 = m0 + mi * 16 + (lane >> 2);
        int r1 = r0 + 8;
        #pragma unroll
        for (int ni = 0; ni < 4; ni++) {
            int co = n0 + ni * 8 + (lane & 3) * 2;
            float* p0 = out + (size_t)(n * 128 + co) * HOWO + ho * Wo;
            float* p1 = p0 + HOWO;
            if (r0 < Wo) { p0[r0] = acc[mi][ni][0]; p1[r0] = acc[mi][ni][1]; }
            if (r1 < Wo) { p0[r1] = acc[mi][ni][2]; p1[r1] = acc[mi][ni][3]; }
        }
    }
}

// ---------------------------------------------------------------------------
extern "C" void kernel_launch(void* const* d_in, const int* in_sizes, int n_in,
                              void* d_out, int out_size) {
    const float* inp   = (const float*)d_in[0];  // [8,128,128,128]
    const float* wgt   = (const float*)d_in[1];  // [128,128,3,3]
    const float* rates = (const float*)d_in[2];  // [1,1,32,32]
    const float* bias  = (const float*)d_in[3];  // [128]
    float* out = (float*)d_out;

    quad_prep<<<(8 * 128 * 128 * 32) / 256, 256>>>(inp);   // 4.19M threads
    wt_prep<<<(9 * 128 * 128 + 255) / 256, 256>>>(wgt);

    dim3 grid(Ho, 8);   // (126, 8) = 1008 CTAs
    adc_mma<<<grid, 256>>>(rates, bias, out);
}